// round 3
// baseline (speedup 1.0000x reference)
#include <cuda_runtime.h>
#include <cuda_bf16.h>
#include <cstdint>
#include <cstddef>

#define BB 4
#define SS 2048
#define DD 1024
#define HH 16
#define MTOK (BB*SS)

// Scratch (no allocs allowed)
__device__ float g_q[MTOK * DD];
__device__ float g_k[MTOK * DD];
__device__ float g_v[MTOK * DD];
__device__ float g_att[MTOK * DD];

// ---------------------------------------------------------------------------
// helpers
// ---------------------------------------------------------------------------
__device__ __forceinline__ void mma16816(float* c, const uint32_t* a, const uint32_t* b) {
    asm volatile(
        "mma.sync.aligned.m16n8k16.row.col.f32.bf16.bf16.f32 "
        "{%0,%1,%2,%3},{%4,%5,%6,%7},{%8,%9},{%0,%1,%2,%3};"
        : "+f"(c[0]), "+f"(c[1]), "+f"(c[2]), "+f"(c[3])
        : "r"(a[0]), "r"(a[1]), "r"(a[2]), "r"(a[3]), "r"(b[0]), "r"(b[1]));
}

__device__ __forceinline__ uint32_t pack_bf16x2(float x, float y) {
    __nv_bfloat162 t = __floats2bfloat162_rn(x, y);
    return *reinterpret_cast<uint32_t*>(&t);
}

// split fp32 -> (bf16 hi, bf16 lo) and store 4 elements
__device__ __forceinline__ void store_split4(__nv_bfloat16* ph, __nv_bfloat16* pl, float4 v) {
    float f[4] = {v.x, v.y, v.z, v.w};
#pragma unroll
    for (int j = 0; j < 4; j += 2) {
        __nv_bfloat16 h0 = __float2bfloat16(f[j]);
        __nv_bfloat16 h1 = __float2bfloat16(f[j + 1]);
        float r0 = f[j]   - __bfloat162float(h0);
        float r1 = f[j+1] - __bfloat162float(h1);
        __nv_bfloat162 hv; hv.x = h0; hv.y = h1;
        *reinterpret_cast<uint32_t*>(ph + j) = *reinterpret_cast<uint32_t*>(&hv);
        *reinterpret_cast<uint32_t*>(pl + j) = pack_bf16x2(r0, r1);
    }
}

__device__ __forceinline__ void ldsm_x2_trans(uint32_t& r0, uint32_t& r1, const void* p) {
    uint32_t addr = (uint32_t)__cvta_generic_to_shared(p);
    asm volatile("ldmatrix.sync.aligned.m8n8.x2.trans.shared.b16 {%0,%1},[%2];"
                 : "=r"(r0), "=r"(r1) : "r"(addr));
}

// ---------------------------------------------------------------------------
// GEMM: C[M,N] = A[M,K] * W[N,K]^T, bf16 2-way split, 3 mmas per product.
// block 128x128, 8 warps (2x4), warp tile 64x32, k-tile 32.
// ---------------------------------------------------------------------------
#define AST 40   // smem row stride in bf16 elems (conflict-free)

__global__ __launch_bounds__(256, 2) void gemm_bf16x3(
    const float* __restrict__ A, const float* __restrict__ W,
    float* __restrict__ C, int M, int N, int K)
{
    __shared__ __align__(16) __nv_bfloat16 sAh[128 * AST];
    __shared__ __align__(16) __nv_bfloat16 sAl[128 * AST];
    __shared__ __align__(16) __nv_bfloat16 sWh[128 * AST];
    __shared__ __align__(16) __nv_bfloat16 sWl[128 * AST];

    const int tid  = threadIdx.x;
    const int lane = tid & 31, w = tid >> 5;
    const int g = lane >> 2, t4 = lane & 3;
    const int m0 = (w >> 2) * 64, n0 = (w & 3) * 32;
    const int bm = blockIdx.y * 128, bn = blockIdx.x * 128;

    float acc[4][4][4];
#pragma unroll
    for (int i = 0; i < 4; ++i)
#pragma unroll
        for (int j = 0; j < 4; ++j)
#pragma unroll
            for (int c = 0; c < 4; ++c) acc[i][j][c] = 0.f;

    for (int kt = 0; kt < K; kt += 32) {
        __syncthreads();
#pragma unroll
        for (int it = 0; it < 4; ++it) {
            int idx = it * 256 + tid;
            int r = idx >> 3, c4 = (idx & 7) << 2;
            float4 av = *(const float4*)(A + (size_t)(bm + r) * K + kt + c4);
            float4 wv = *(const float4*)(W + (size_t)(bn + r) * K + kt + c4);
            store_split4(&sAh[r * AST + c4], &sAl[r * AST + c4], av);
            store_split4(&sWh[r * AST + c4], &sWl[r * AST + c4], wv);
        }
        __syncthreads();

#pragma unroll
        for (int ks = 0; ks < 32; ks += 16) {
            uint32_t ah[4][4], al[4][4];
#pragma unroll
            for (int mt = 0; mt < 4; ++mt) {
                int rb = (m0 + mt * 16 + g) * AST + ks + 2 * t4;
                ah[mt][0] = *(const uint32_t*)&sAh[rb];
                ah[mt][1] = *(const uint32_t*)&sAh[rb + 8 * AST];
                ah[mt][2] = *(const uint32_t*)&sAh[rb + 8];
                ah[mt][3] = *(const uint32_t*)&sAh[rb + 8 * AST + 8];
                al[mt][0] = *(const uint32_t*)&sAl[rb];
                al[mt][1] = *(const uint32_t*)&sAl[rb + 8 * AST];
                al[mt][2] = *(const uint32_t*)&sAl[rb + 8];
                al[mt][3] = *(const uint32_t*)&sAl[rb + 8 * AST + 8];
            }
#pragma unroll
            for (int nt = 0; nt < 4; ++nt) {
                int rb = (n0 + nt * 8 + g) * AST + ks + 2 * t4;
                uint32_t bh[2] = { *(const uint32_t*)&sWh[rb], *(const uint32_t*)&sWh[rb + 8] };
                uint32_t bl[2] = { *(const uint32_t*)&sWl[rb], *(const uint32_t*)&sWl[rb + 8] };
#pragma unroll
                for (int mt = 0; mt < 4; ++mt) {
                    mma16816(acc[mt][nt], ah[mt], bh);
                    mma16816(acc[mt][nt], ah[mt], bl);
                    mma16816(acc[mt][nt], al[mt], bh);
                }
            }
        }
    }

#pragma unroll
    for (int mt = 0; mt < 4; ++mt)
#pragma unroll
        for (int nt = 0; nt < 4; ++nt) {
            int row = bm + m0 + mt * 16 + g;
            int col = bn + n0 + nt * 8 + 2 * t4;
            *(float2*)(C + (size_t)row * N + col) =
                make_float2(acc[mt][nt][0], acc[mt][nt][1]);
            *(float2*)(C + (size_t)(row + 8) * N + col) =
                make_float2(acc[mt][nt][2], acc[mt][nt][3]);
        }
}

// ---------------------------------------------------------------------------
// Fused attention, bf16x3 mma. Block = (b, h, 64-query tile), 4 warps,
// warp owns 16 query rows. K smem buffer is reused for P between phases.
// ---------------------------------------------------------------------------
#define TS 72    // smem row stride in bf16 elems

__global__ __launch_bounds__(128) void attn_bf16x3(
    const float* __restrict__ Q, const float* __restrict__ Kx,
    const float* __restrict__ V, const int* __restrict__ mask,
    float* __restrict__ O)
{
    extern __shared__ __align__(16) __nv_bfloat16 sm[];
    __nv_bfloat16* sQh = sm;
    __nv_bfloat16* sQl = sQh + 64 * TS;
    __nv_bfloat16* sKh = sQl + 64 * TS;   // reused for P (hi)
    __nv_bfloat16* sKl = sKh + 64 * TS;   // reused for P (lo)
    __nv_bfloat16* sVh = sKl + 64 * TS;
    __nv_bfloat16* sVl = sVh + 64 * TS;

    const int b = blockIdx.z, h = blockIdx.y, s0 = blockIdx.x * 64;
    const int tid = threadIdx.x, lane = tid & 31, w = tid >> 5;
    const int g = lane >> 2, t4 = lane & 3;
    const int m0 = w * 16;

    // stage Q tile (split)
    const float* qb = Q + (size_t)(b * SS + s0) * DD + h * 64;
#pragma unroll
    for (int it = 0; it < 8; ++it) {
        int idx = it * 128 + tid;
        int r = idx >> 4, c4 = (idx & 15) << 2;
        float4 v = *(const float4*)(qb + (size_t)r * DD + c4);
        store_split4(&sQh[r * TS + c4], &sQl[r * TS + c4], v);
    }

    float m_i[2] = {-1e30f, -1e30f}, l_i[2] = {0.f, 0.f};
    float oacc[8][4];
#pragma unroll
    for (int nt = 0; nt < 8; ++nt)
#pragma unroll
        for (int c = 0; c < 4; ++c) oacc[nt][c] = 0.f;

    const int* mrow0 = mask + ((size_t)b * SS + s0 + m0 + g) * SS;
    const int* mrow8 = mrow0 + (size_t)8 * SS;

    for (int t0 = 0; t0 < SS; t0 += 64) {
        __syncthreads();
        const float* kb = Kx + (size_t)(b * SS + t0) * DD + h * 64;
        const float* vb = V  + (size_t)(b * SS + t0) * DD + h * 64;
#pragma unroll
        for (int it = 0; it < 8; ++it) {
            int idx = it * 128 + tid;
            int r = idx >> 4, c4 = (idx & 15) << 2;
            float4 kv = *(const float4*)(kb + (size_t)r * DD + c4);
            store_split4(&sKh[r * TS + c4], &sKl[r * TS + c4], kv);
            float4 vv = *(const float4*)(vb + (size_t)r * DD + c4);
            store_split4(&sVh[r * TS + c4], &sVl[r * TS + c4], vv);
        }
        __syncthreads();

        // ---- scores S = Q K^T (16x64 per warp) ----
        float sc[8][4];
#pragma unroll
        for (int nt = 0; nt < 8; ++nt)
#pragma unroll
            for (int c = 0; c < 4; ++c) sc[nt][c] = 0.f;

#pragma unroll
        for (int ks = 0; ks < 64; ks += 16) {
            uint32_t qh[4], ql[4];
            int rb = (m0 + g) * TS + ks + 2 * t4;
            qh[0] = *(const uint32_t*)&sQh[rb];
            qh[1] = *(const uint32_t*)&sQh[rb + 8 * TS];
            qh[2] = *(const uint32_t*)&sQh[rb + 8];
            qh[3] = *(const uint32_t*)&sQh[rb + 8 * TS + 8];
            ql[0] = *(const uint32_t*)&sQl[rb];
            ql[1] = *(const uint32_t*)&sQl[rb + 8 * TS];
            ql[2] = *(const uint32_t*)&sQl[rb + 8];
            ql[3] = *(const uint32_t*)&sQl[rb + 8 * TS + 8];
#pragma unroll
            for (int nt = 0; nt < 8; ++nt) {
                int kb2 = (nt * 8 + g) * TS + ks + 2 * t4;
                uint32_t bh[2] = { *(const uint32_t*)&sKh[kb2], *(const uint32_t*)&sKh[kb2 + 8] };
                uint32_t bl[2] = { *(const uint32_t*)&sKl[kb2], *(const uint32_t*)&sKl[kb2 + 8] };
                mma16816(sc[nt], qh, bh);
                mma16816(sc[nt], qh, bl);
                mma16816(sc[nt], ql, bh);
            }
        }

        // ---- mask + scale + online softmax ----
        float mx0 = -1e30f, mx1 = -1e30f;
#pragma unroll
        for (int nt = 0; nt < 8; ++nt) {
            int tcol = t0 + nt * 8 + 2 * t4;
            int2 mk0 = *(const int2*)(mrow0 + tcol);
            int2 mk1 = *(const int2*)(mrow8 + tcol);
            sc[nt][0] = mk0.x ? sc[nt][0] * 0.125f : -1e10f;
            sc[nt][1] = mk0.y ? sc[nt][1] * 0.125f : -1e10f;
            sc[nt][2] = mk1.x ? sc[nt][2] * 0.125f : -1e10f;
            sc[nt][3] = mk1.y ? sc[nt][3] * 0.125f : -1e10f;
            mx0 = fmaxf(mx0, fmaxf(sc[nt][0], sc[nt][1]));
            mx1 = fmaxf(mx1, fmaxf(sc[nt][2], sc[nt][3]));
        }
        mx0 = fmaxf(mx0, __shfl_xor_sync(0xffffffffu, mx0, 1));
        mx0 = fmaxf(mx0, __shfl_xor_sync(0xffffffffu, mx0, 2));
        mx1 = fmaxf(mx1, __shfl_xor_sync(0xffffffffu, mx1, 1));
        mx1 = fmaxf(mx1, __shfl_xor_sync(0xffffffffu, mx1, 2));

        float mn0 = fmaxf(m_i[0], mx0), mn1 = fmaxf(m_i[1], mx1);
        float corr0 = __expf(m_i[0] - mn0), corr1 = __expf(m_i[1] - mn1);
        m_i[0] = mn0; m_i[1] = mn1;

        float sum0 = 0.f, sum1 = 0.f;
#pragma unroll
        for (int nt = 0; nt < 8; ++nt) {
            sc[nt][0] = __expf(sc[nt][0] - mn0);
            sc[nt][1] = __expf(sc[nt][1] - mn0);
            sc[nt][2] = __expf(sc[nt][2] - mn1);
            sc[nt][3] = __expf(sc[nt][3] - mn1);
            sum0 += sc[nt][0] + sc[nt][1];
            sum1 += sc[nt][2] + sc[nt][3];
        }
        sum0 += __shfl_xor_sync(0xffffffffu, sum0, 1);
        sum0 += __shfl_xor_sync(0xffffffffu, sum0, 2);
        sum1 += __shfl_xor_sync(0xffffffffu, sum1, 1);
        sum1 += __shfl_xor_sync(0xffffffffu, sum1, 2);
        l_i[0] = l_i[0] * corr0 + sum0;
        l_i[1] = l_i[1] * corr1 + sum1;
#pragma unroll
        for (int nt = 0; nt < 8; ++nt) {
            oacc[nt][0] *= corr0; oacc[nt][1] *= corr0;
            oacc[nt][2] *= corr1; oacc[nt][3] *= corr1;
        }

        __syncthreads();  // all warps done reading K before P overwrites it

        // ---- write P (split) into K buffers ----
#pragma unroll
        for (int nt = 0; nt < 8; ++nt) {
            int pr = (m0 + g) * TS + nt * 8 + 2 * t4;
            float e0 = sc[nt][0], e1 = sc[nt][1];
            float h0 = __bfloat162float(__float2bfloat16(e0));
            float h1 = __bfloat162float(__float2bfloat16(e1));
            *(uint32_t*)&sKh[pr] = pack_bf16x2(e0, e1);
            *(uint32_t*)&sKl[pr] = pack_bf16x2(e0 - h0, e1 - h1);
            float e2 = sc[nt][2], e3 = sc[nt][3];
            float h2 = __bfloat162float(__float2bfloat16(e2));
            float h3 = __bfloat162float(__float2bfloat16(e3));
            *(uint32_t*)&sKh[pr + 8 * TS] = pack_bf16x2(e2, e3);
            *(uint32_t*)&sKl[pr + 8 * TS] = pack_bf16x2(e2 - h2, e3 - h3);
        }
        __syncthreads();

        // ---- O += P V ----
#pragma unroll
        for (int ks = 0; ks < 64; ks += 16) {
            uint32_t ph[4], pl[4];
            int rb = (m0 + g) * TS + ks + 2 * t4;
            ph[0] = *(const uint32_t*)&sKh[rb];
            ph[1] = *(const uint32_t*)&sKh[rb + 8 * TS];
            ph[2] = *(const uint32_t*)&sKh[rb + 8];
            ph[3] = *(const uint32_t*)&sKh[rb + 8 * TS + 8];
            pl[0] = *(const uint32_t*)&sKl[rb];
            pl[1] = *(const uint32_t*)&sKl[rb + 8 * TS];
            pl[2] = *(const uint32_t*)&sKl[rb + 8];
            pl[3] = *(const uint32_t*)&sKl[rb + 8 * TS + 8];

            int vrow = ks + (lane & 15);
#pragma unroll
            for (int nt = 0; nt < 8; ++nt) {
                uint32_t vh[2], vl[2];
                ldsm_x2_trans(vh[0], vh[1], &sVh[vrow * TS + nt * 8]);
                ldsm_x2_trans(vl[0], vl[1], &sVl[vrow * TS + nt * 8]);
                mma16816(oacc[nt], ph, vh);
                mma16816(oacc[nt], ph, vl);
                mma16816(oacc[nt], pl, vh);
            }
        }
    }

    // ---- epilogue ----
    float inv0 = __fdividef(1.f, l_i[0]);
    float inv1 = __fdividef(1.f, l_i[1]);
    float* ob = O + (size_t)(b * SS + s0 + m0 + g) * DD + h * 64;
#pragma unroll
    for (int nt = 0; nt < 8; ++nt) {
        int col = nt * 8 + 2 * t4;
        *(float2*)(ob + col) = make_float2(oacc[nt][0] * inv0, oacc[nt][1] * inv0);
        *(float2*)(ob + (size_t)8 * DD + col) = make_float2(oacc[nt][2] * inv1, oacc[nt][3] * inv1);
    }
}

// ---------------------------------------------------------------------------
extern "C" void kernel_launch(void* const* d_in, const int* in_sizes, int n_in,
                              void* d_out, int out_size)
{
    const float* queries = (const float*)d_in[0];
    const float* keys    = (const float*)d_in[1];
    const float* values  = (const float*)d_in[2];
    const int*   mask    = (const int*)  d_in[3];
    const float* Wq      = (const float*)d_in[4];
    const float* Wk      = (const float*)d_in[5];
    const float* Wv      = (const float*)d_in[6];
    const float* Wo      = (const float*)d_in[7];
    float* out = (float*)d_out;

    float *gq, *gk, *gv, *go;
    cudaGetSymbolAddress((void**)&gq, g_q);
    cudaGetSymbolAddress((void**)&gk, g_k);
    cudaGetSymbolAddress((void**)&gv, g_v);
    cudaGetSymbolAddress((void**)&go, g_att);

    const int SMEM_ATTN = 6 * 64 * TS * (int)sizeof(__nv_bfloat16);
    cudaFuncSetAttribute(attn_bf16x3, cudaFuncAttributeMaxDynamicSharedMemorySize, SMEM_ATTN);

    dim3 gg(DD / 128, MTOK / 128);  // (8, 64)

    gemm_bf16x3<<<gg, 256>>>(queries, Wq, gq, MTOK, DD, DD);
    gemm_bf16x3<<<gg, 256>>>(keys,    Wk, gk, MTOK, DD, DD);
    gemm_bf16x3<<<gg, 256>>>(values,  Wv, gv, MTOK, DD, DD);

    attn_bf16x3<<<dim3(SS / 64, HH, BB), 128, SMEM_ATTN>>>(gq, gk, gv, mask, go);

    gemm_bf16x3<<<gg, 256>>>(go, Wo, out, MTOK, DD, DD);
}

// round 5
// speedup vs baseline: 1.0332x; 1.0332x over previous
#include <cuda_runtime.h>
#include <cuda_bf16.h>
#include <cstdint>
#include <cstddef>

#define BB 4
#define SS 2048
#define DD 1024
#define HH 16
#define MTOK (BB*SS)

// ---------------- scratch (__device__ globals; allocs forbidden) ----------
__device__ __nv_bfloat16 g_xqh[MTOK*DD], g_xql[MTOK*DD];
__device__ __nv_bfloat16 g_xkh[MTOK*DD], g_xkl[MTOK*DD];
__device__ __nv_bfloat16 g_xvh[MTOK*DD], g_xvl[MTOK*DD];
__device__ __nv_bfloat16 g_wqh[DD*DD], g_wql[DD*DD];
__device__ __nv_bfloat16 g_wkh[DD*DD], g_wkl[DD*DD];
__device__ __nv_bfloat16 g_wvh[DD*DD], g_wvl[DD*DD];
__device__ __nv_bfloat16 g_woh[DD*DD], g_wol[DD*DD];
__device__ __nv_bfloat16 g_qh[MTOK*DD], g_ql[MTOK*DD];
__device__ __nv_bfloat16 g_kh[MTOK*DD], g_kl[MTOK*DD];
__device__ __nv_bfloat16 g_vh[MTOK*DD], g_vl[MTOK*DD];
__device__ __nv_bfloat16 g_oh[MTOK*DD], g_ol[MTOK*DD];
__device__ uint32_t g_mbits[(size_t)BB*SS*(SS/32)];

// ---------------- helpers --------------------------------------------------
__device__ __forceinline__ uint32_t smem_u32(const void* p) {
    return (uint32_t)__cvta_generic_to_shared(p);
}
__device__ __forceinline__ void mma16816(float* c, const uint32_t* a, const uint32_t* b) {
    asm volatile(
        "mma.sync.aligned.m16n8k16.row.col.f32.bf16.bf16.f32 "
        "{%0,%1,%2,%3},{%4,%5,%6,%7},{%8,%9},{%0,%1,%2,%3};"
        : "+f"(c[0]), "+f"(c[1]), "+f"(c[2]), "+f"(c[3])
        : "r"(a[0]), "r"(a[1]), "r"(a[2]), "r"(a[3]), "r"(b[0]), "r"(b[1]));
}
__device__ __forceinline__ void ldsm_x4(uint32_t* r, const void* p) {
    uint32_t a = smem_u32(p);
    asm volatile("ldmatrix.sync.aligned.m8n8.x4.shared.b16 {%0,%1,%2,%3},[%4];"
                 : "=r"(r[0]), "=r"(r[1]), "=r"(r[2]), "=r"(r[3]) : "r"(a));
}
__device__ __forceinline__ void ldsm_x2(uint32_t* r, const void* p) {
    uint32_t a = smem_u32(p);
    asm volatile("ldmatrix.sync.aligned.m8n8.x2.shared.b16 {%0,%1},[%2];"
                 : "=r"(r[0]), "=r"(r[1]) : "r"(a));
}
__device__ __forceinline__ void ldsm_x2t(uint32_t* r, const void* p) {
    uint32_t a = smem_u32(p);
    asm volatile("ldmatrix.sync.aligned.m8n8.x2.trans.shared.b16 {%0,%1},[%2];"
                 : "=r"(r[0]), "=r"(r[1]) : "r"(a));
}
__device__ __forceinline__ void split2(float f0, float f1, uint32_t& hi, uint32_t& lo) {
    __nv_bfloat162 h = __floats2bfloat162_rn(f0, f1);
    float r0 = f0 - __bfloat162float(h.x);
    float r1 = f1 - __bfloat162float(h.y);
    hi = *reinterpret_cast<uint32_t*>(&h);
    __nv_bfloat162 l = __floats2bfloat162_rn(r0, r1);
    lo = *reinterpret_cast<uint32_t*>(&l);
}
__device__ __forceinline__ void cp16(void* s, const void* g) {
    uint32_t sa = smem_u32(s);
    asm volatile("cp.async.cg.shared.global [%0], [%1], 16;" :: "r"(sa), "l"(g));
}
#define CP_COMMIT() asm volatile("cp.async.commit_group;" ::: "memory")
#define CP_WAIT(n)  asm volatile("cp.async.wait_group %0;" :: "n"(n) : "memory")

// ---------------- prepass kernels ------------------------------------------
__global__ void split_kernel(const float4* __restrict__ x, uint2* __restrict__ h,
                             uint2* __restrict__ l, int n4) {
    int i = blockIdx.x * 256 + threadIdx.x;
    if (i < n4) {
        float4 v = x[i];
        uint2 hh, ll;
        split2(v.x, v.y, hh.x, ll.x);
        split2(v.z, v.w, hh.y, ll.y);
        h[i] = hh; l[i] = ll;
    }
}
__global__ void maskbits_kernel(const int* __restrict__ m, uint32_t* __restrict__ bits) {
    size_t w = (size_t)blockIdx.x * 8 + (threadIdx.x >> 5);
    int lane = threadIdx.x & 31;
    int v = m[w * 32 + lane];
    uint32_t b = __ballot_sync(0xffffffffu, v != 0);
    if (lane == 0) bits[w] = b;
}

// ---------------- GEMM (mma.sync bf16x3, cp.async pipeline) ----------------
// C[M,N] = A[M,K] * W[N,K]^T, inputs pre-split (hi/lo).
// Block 128x128, 8 warps (2x4), warp tile 64x32, k-tile 32, double buffer.
#define GST 40                      // smem row stride (bf16)
#define GMAT (128*GST)              // elems per matrix buffer
#define GBUFE (4*GMAT)              // elems per stage buffer (Ah,Al,Wh,Wl)

__global__ __launch_bounds__(256, 1) void gemm_mma(
    const __nv_bfloat16* __restrict__ Ah, const __nv_bfloat16* __restrict__ Al,
    const __nv_bfloat16* __restrict__ Wh, const __nv_bfloat16* __restrict__ Wl,
    float* __restrict__ Cf, __nv_bfloat16* __restrict__ Ch, __nv_bfloat16* __restrict__ Cl,
    int M, int N, int K, int split_out)
{
    extern __shared__ __align__(16) __nv_bfloat16 sg[];   // [2][4][128*GST]

    const int tid = threadIdx.x, lane = tid & 31, w = tid >> 5;
    const int g = lane >> 2, t4 = lane & 3, l15 = lane & 15;
    const int m0 = (w >> 2) * 64, n0 = (w & 3) * 32;
    const int bm = blockIdx.y * 128, bn = blockIdx.x * 128;

    const __nv_bfloat16* mats[4] = { Ah + (size_t)bm * K, Al + (size_t)bm * K,
                                     Wh + (size_t)bn * K, Wl + (size_t)bn * K };

    auto stage = [&](int buf, int k0) {
#pragma unroll
        for (int it = 0; it < 8; ++it) {
            int c = it * 256 + tid;
            int mat = c >> 9, r = (c >> 2) & 127, u = c & 3;
            cp16(&sg[buf * GBUFE + mat * GMAT + r * GST + u * 8],
                 mats[mat] + (size_t)r * K + k0 + u * 8);
        }
    };

    float acc[4][4][4];
#pragma unroll
    for (int i = 0; i < 4; ++i)
#pragma unroll
        for (int j = 0; j < 4; ++j)
#pragma unroll
            for (int c = 0; c < 4; ++c) acc[i][j][c] = 0.f;

    stage(0, 0); CP_COMMIT();

    const int NST = K / 32;
    for (int kt = 0; kt < NST; ++kt) {
        int buf = kt & 1;
        if (kt + 1 < NST) { stage(buf ^ 1, (kt + 1) * 32); CP_COMMIT(); CP_WAIT(1); }
        else CP_WAIT(0);
        __syncthreads();

        const __nv_bfloat16* bAh = &sg[buf * GBUFE];
        const __nv_bfloat16* bAl = bAh + GMAT;
        const __nv_bfloat16* bWh = bAl + GMAT;
        const __nv_bfloat16* bWl = bWh + GMAT;

#pragma unroll
        for (int ks = 0; ks < 32; ks += 16) {
            uint32_t ah[4][4], al[4][4];
#pragma unroll
            for (int mt = 0; mt < 4; ++mt) {
                const int ro = (m0 + mt * 16 + l15) * GST + ks + (lane >> 4) * 8;
                ldsm_x4(ah[mt], bAh + ro);
                ldsm_x4(al[mt], bAl + ro);
            }
#pragma unroll
            for (int nt = 0; nt < 4; ++nt) {
                const int ro = (n0 + nt * 8 + (lane & 7)) * GST + ks + ((lane >> 3) & 1) * 8;
                uint32_t bh[2], bl[2];
                ldsm_x2(bh, bWh + ro);
                ldsm_x2(bl, bWl + ro);
#pragma unroll
                for (int mt = 0; mt < 4; ++mt) {
                    mma16816(acc[mt][nt], ah[mt], bh);
                    mma16816(acc[mt][nt], ah[mt], bl);
                    mma16816(acc[mt][nt], al[mt], bh);
                }
            }
        }
        __syncthreads();
    }

#pragma unroll
    for (int mt = 0; mt < 4; ++mt)
#pragma unroll
        for (int nt = 0; nt < 4; ++nt) {
            int row = bm + m0 + mt * 16 + g;
            int col = bn + n0 + nt * 8 + 2 * t4;
            if (split_out) {
                uint32_t hh, ll;
                split2(acc[mt][nt][0], acc[mt][nt][1], hh, ll);
                *(uint32_t*)&Ch[(size_t)row * N + col] = hh;
                *(uint32_t*)&Cl[(size_t)row * N + col] = ll;
                split2(acc[mt][nt][2], acc[mt][nt][3], hh, ll);
                *(uint32_t*)&Ch[(size_t)(row + 8) * N + col] = hh;
                *(uint32_t*)&Cl[(size_t)(row + 8) * N + col] = ll;
            } else {
                *(float2*)(Cf + (size_t)row * N + col) =
                    make_float2(acc[mt][nt][0], acc[mt][nt][1]);
                *(float2*)(Cf + (size_t)(row + 8) * N + col) =
                    make_float2(acc[mt][nt][2], acc[mt][nt][3]);
            }
        }
}

// ---------------- fused attention (bf16x3 mma, pre-split, bitmask) ---------
#define TS 72
__global__ __launch_bounds__(128) void attn_tc(
    const __nv_bfloat16* __restrict__ Qh, const __nv_bfloat16* __restrict__ Ql,
    const __nv_bfloat16* __restrict__ Kh, const __nv_bfloat16* __restrict__ Kl,
    const __nv_bfloat16* __restrict__ Vh, const __nv_bfloat16* __restrict__ Vl,
    const uint32_t* __restrict__ mbits,
    __nv_bfloat16* __restrict__ Oh, __nv_bfloat16* __restrict__ Ol)
{
    extern __shared__ __align__(16) __nv_bfloat16 sm[];
    __nv_bfloat16* sQh = sm;
    __nv_bfloat16* sQl = sQh + 64 * TS;
    __nv_bfloat16* sKh = sQl + 64 * TS;
    __nv_bfloat16* sKl = sKh + 64 * TS;
    __nv_bfloat16* sVh = sKl + 64 * TS;
    __nv_bfloat16* sVl = sVh + 64 * TS;

    const int b = blockIdx.z, h = blockIdx.y, s0 = blockIdx.x * 64;
    const int tid = threadIdx.x, lane = tid & 31, w = tid >> 5;
    const int g = lane >> 2, t4 = lane & 3;
    const int m0 = w * 16, l15 = lane & 15;

    const __nv_bfloat16* qhp = Qh + (size_t)(b * SS + s0) * DD + h * 64;
    const __nv_bfloat16* qlp = Ql + (size_t)(b * SS + s0) * DD + h * 64;
#pragma unroll
    for (int it = 0; it < 4; ++it) {
        int idx = it * 128 + tid;
        int r = idx >> 3, u = idx & 7;
        cp16(&sQh[r * TS + u * 8], qhp + (size_t)r * DD + u * 8);
        cp16(&sQl[r * TS + u * 8], qlp + (size_t)r * DD + u * 8);
    }
    CP_COMMIT();

    float m_i[2] = {-1e30f, -1e30f}, l_i[2] = {0.f, 0.f};
    float oacc[8][4];
#pragma unroll
    for (int nt = 0; nt < 8; ++nt)
#pragma unroll
        for (int c = 0; c < 4; ++c) oacc[nt][c] = 0.f;

    const uint32_t* mb0 = mbits + ((size_t)b * SS + s0 + m0 + g) * (SS / 32);
    const uint32_t* mb8 = mb0 + 8 * (SS / 32);

    for (int t0 = 0; t0 < SS; t0 += 64) {
        __syncthreads();   // prior-iteration V reads complete
        const __nv_bfloat16* khp = Kh + (size_t)(b * SS + t0) * DD + h * 64;
        const __nv_bfloat16* klp = Kl + (size_t)(b * SS + t0) * DD + h * 64;
        const __nv_bfloat16* vhp = Vh + (size_t)(b * SS + t0) * DD + h * 64;
        const __nv_bfloat16* vlp = Vl + (size_t)(b * SS + t0) * DD + h * 64;
#pragma unroll
        for (int it = 0; it < 4; ++it) {
            int idx = it * 128 + tid;
            int r = idx >> 3, u = idx & 7;
            cp16(&sKh[r * TS + u * 8], khp + (size_t)r * DD + u * 8);
            cp16(&sKl[r * TS + u * 8], klp + (size_t)r * DD + u * 8);
            cp16(&sVh[r * TS + u * 8], vhp + (size_t)r * DD + u * 8);
            cp16(&sVl[r * TS + u * 8], vlp + (size_t)r * DD + u * 8);
        }
        CP_COMMIT();
        CP_WAIT(0);
        __syncthreads();

        // ---- S = Q K^T ----
        float sc[8][4];
#pragma unroll
        for (int nt = 0; nt < 8; ++nt)
#pragma unroll
            for (int c = 0; c < 4; ++c) sc[nt][c] = 0.f;

#pragma unroll
        for (int ks = 0; ks < 64; ks += 16) {
            uint32_t qfh[4], qfl[4];
            ldsm_x4(qfh, &sQh[(m0 + l15) * TS + ks + (lane >> 4) * 8]);
            ldsm_x4(qfl, &sQl[(m0 + l15) * TS + ks + (lane >> 4) * 8]);
#pragma unroll
            for (int nt = 0; nt < 8; ++nt) {
                uint32_t bh[2], bl[2];
                const int ko = ks + ((lane >> 3) & 1) * 8;
                ldsm_x2(bh, &sKh[(nt * 8 + (lane & 7)) * TS + ko]);
                ldsm_x2(bl, &sKl[(nt * 8 + (lane & 7)) * TS + ko]);
                mma16816(sc[nt], qfh, bh);
                mma16816(sc[nt], qfh, bl);
                mma16816(sc[nt], qfl, bh);
            }
        }

        // ---- mask + scale ----
        uint32_t wa0 = mb0[t0 >> 5], wb0 = mb0[(t0 >> 5) + 1];
        uint32_t wa8 = mb8[t0 >> 5], wb8 = mb8[(t0 >> 5) + 1];
        if ((wa0 & wb0 & wa8 & wb8) == 0xffffffffu) {
#pragma unroll
            for (int nt = 0; nt < 8; ++nt)
#pragma unroll
                for (int c = 0; c < 4; ++c) sc[nt][c] *= 0.125f;
        } else {
#pragma unroll
            for (int nt = 0; nt < 8; ++nt) {
                int c = nt * 8 + 2 * t4;
                uint32_t s0w = (c & 32) ? wb0 : wa0;
                uint32_t s8w = (c & 32) ? wb8 : wa8;
                int sh = c & 31;
                sc[nt][0] = ((s0w >> sh) & 1) ? sc[nt][0] * 0.125f : -1e10f;
                sc[nt][1] = ((s0w >> (sh + 1)) & 1) ? sc[nt][1] * 0.125f : -1e10f;
                sc[nt][2] = ((s8w >> sh) & 1) ? sc[nt][2] * 0.125f : -1e10f;
                sc[nt][3] = ((s8w >> (sh + 1)) & 1) ? sc[nt][3] * 0.125f : -1e10f;
            }
        }

        // ---- online softmax ----
        float mx0 = -1e30f, mx1 = -1e30f;
#pragma unroll
        for (int nt = 0; nt < 8; ++nt) {
            mx0 = fmaxf(mx0, fmaxf(sc[nt][0], sc[nt][1]));
            mx1 = fmaxf(mx1, fmaxf(sc[nt][2], sc[nt][3]));
        }
        mx0 = fmaxf(mx0, __shfl_xor_sync(0xffffffffu, mx0, 1));
        mx0 = fmaxf(mx0, __shfl_xor_sync(0xffffffffu, mx0, 2));
        mx1 = fmaxf(mx1, __shfl_xor_sync(0xffffffffu, mx1, 1));
        mx1 = fmaxf(mx1, __shfl_xor_sync(0xffffffffu, mx1, 2));

        float mn0 = fmaxf(m_i[0], mx0), mn1 = fmaxf(m_i[1], mx1);
        float corr0 = __expf(m_i[0] - mn0), corr1 = __expf(m_i[1] - mn1);
        m_i[0] = mn0; m_i[1] = mn1;

        float sum0 = 0.f, sum1 = 0.f;
#pragma unroll
        for (int nt = 0; nt < 8; ++nt) {
            sc[nt][0] = __expf(sc[nt][0] - mn0);
            sc[nt][1] = __expf(sc[nt][1] - mn0);
            sc[nt][2] = __expf(sc[nt][2] - mn1);
            sc[nt][3] = __expf(sc[nt][3] - mn1);
            sum0 += sc[nt][0] + sc[nt][1];
            sum1 += sc[nt][2] + sc[nt][3];
        }
        sum0 += __shfl_xor_sync(0xffffffffu, sum0, 1);
        sum0 += __shfl_xor_sync(0xffffffffu, sum0, 2);
        sum1 += __shfl_xor_sync(0xffffffffu, sum1, 1);
        sum1 += __shfl_xor_sync(0xffffffffu, sum1, 2);
        l_i[0] = l_i[0] * corr0 + sum0;
        l_i[1] = l_i[1] * corr1 + sum1;
#pragma unroll
        for (int nt = 0; nt < 8; ++nt) {
            oacc[nt][0] *= corr0; oacc[nt][1] *= corr0;
            oacc[nt][2] *= corr1; oacc[nt][3] *= corr1;
        }

        // ---- O += P V : P stays in registers (C-frag == A-frag layout) ----
#pragma unroll
        for (int j = 0; j < 4; ++j) {
            uint32_t ph[4], pl[4];
            split2(sc[2*j][0],   sc[2*j][1],   ph[0], pl[0]);
            split2(sc[2*j][2],   sc[2*j][3],   ph[1], pl[1]);
            split2(sc[2*j+1][0], sc[2*j+1][1], ph[2], pl[2]);
            split2(sc[2*j+1][2], sc[2*j+1][3], ph[3], pl[3]);
            int vrow = j * 16 + l15;
#pragma unroll
            for (int nt = 0; nt < 8; ++nt) {
                uint32_t vh[2], vl[2];
                ldsm_x2t(vh, &sVh[vrow * TS + nt * 8]);
                ldsm_x2t(vl, &sVl[vrow * TS + nt * 8]);
                mma16816(oacc[nt], ph, vh);
                mma16816(oacc[nt], ph, vl);
                mma16816(oacc[nt], pl, vh);
            }
        }
    }

    // ---- epilogue: normalize, split, store bf16 hi/lo ----
    float inv0 = __fdividef(1.f, l_i[0]);
    float inv1 = __fdividef(1.f, l_i[1]);
    size_t r0 = (size_t)(b * SS + s0 + m0 + g) * DD + h * 64;
    size_t r8 = r0 + (size_t)8 * DD;
#pragma unroll
    for (int nt = 0; nt < 8; ++nt) {
        int col = nt * 8 + 2 * t4;
        uint32_t hh, ll;
        split2(oacc[nt][0] * inv0, oacc[nt][1] * inv0, hh, ll);
        *(uint32_t*)&Oh[r0 + col] = hh; *(uint32_t*)&Ol[r0 + col] = ll;
        split2(oacc[nt][2] * inv1, oacc[nt][3] * inv1, hh, ll);
        *(uint32_t*)&Oh[r8 + col] = hh; *(uint32_t*)&Ol[r8 + col] = ll;
    }
}

// ---------------------------------------------------------------------------
extern "C" void kernel_launch(void* const* d_in, const int* in_sizes, int n_in,
                              void* d_out, int out_size)
{
    const float* queries = (const float*)d_in[0];
    const float* keys    = (const float*)d_in[1];
    const float* values  = (const float*)d_in[2];
    const int*   mask    = (const int*)  d_in[3];
    const float* Wq = (const float*)d_in[4];
    const float* Wk = (const float*)d_in[5];
    const float* Wv = (const float*)d_in[6];
    const float* Wo = (const float*)d_in[7];
    float* out = (float*)d_out;

    __nv_bfloat16 *xqh,*xql,*xkh,*xkl,*xvh,*xvl, *wqh,*wql,*wkh,*wkl,*wvh,*wvl,*woh,*wol;
    __nv_bfloat16 *qh,*ql,*kh,*kl,*vh,*vl,*oh,*ol;
    uint32_t* mb;
    cudaGetSymbolAddress((void**)&xqh, g_xqh); cudaGetSymbolAddress((void**)&xql, g_xql);
    cudaGetSymbolAddress((void**)&xkh, g_xkh); cudaGetSymbolAddress((void**)&xkl, g_xkl);
    cudaGetSymbolAddress((void**)&xvh, g_xvh); cudaGetSymbolAddress((void**)&xvl, g_xvl);
    cudaGetSymbolAddress((void**)&wqh, g_wqh); cudaGetSymbolAddress((void**)&wql, g_wql);
    cudaGetSymbolAddress((void**)&wkh, g_wkh); cudaGetSymbolAddress((void**)&wkl, g_wkl);
    cudaGetSymbolAddress((void**)&wvh, g_wvh); cudaGetSymbolAddress((void**)&wvl, g_wvl);
    cudaGetSymbolAddress((void**)&woh, g_woh); cudaGetSymbolAddress((void**)&wol, g_wol);
    cudaGetSymbolAddress((void**)&qh, g_qh); cudaGetSymbolAddress((void**)&ql, g_ql);
    cudaGetSymbolAddress((void**)&kh, g_kh); cudaGetSymbolAddress((void**)&kl, g_kl);
    cudaGetSymbolAddress((void**)&vh, g_vh); cudaGetSymbolAddress((void**)&vl, g_vl);
    cudaGetSymbolAddress((void**)&oh, g_oh); cudaGetSymbolAddress((void**)&ol, g_ol);
    cudaGetSymbolAddress((void**)&mb, g_mbits);

    const int GEMM_SMEM = 2 * GBUFE * (int)sizeof(__nv_bfloat16);   // 81920
    cudaFuncSetAttribute(gemm_mma, cudaFuncAttributeMaxDynamicSharedMemorySize, GEMM_SMEM);
    const int ATTN_SMEM = 6 * 64 * TS * (int)sizeof(__nv_bfloat16);
    cudaFuncSetAttribute(attn_tc, cudaFuncAttributeMaxDynamicSharedMemorySize, ATTN_SMEM);

    const int n4i = MTOK * DD / 4, n4w = DD * DD / 4;
    split_kernel<<<n4i / 256, 256>>>((const float4*)queries, (uint2*)xqh, (uint2*)xql, n4i);
    split_kernel<<<n4i / 256, 256>>>((const float4*)keys,    (uint2*)xkh, (uint2*)xkl, n4i);
    split_kernel<<<n4i / 256, 256>>>((const float4*)values,  (uint2*)xvh, (uint2*)xvl, n4i);
    split_kernel<<<n4w / 256, 256>>>((const float4*)Wq, (uint2*)wqh, (uint2*)wql, n4w);
    split_kernel<<<n4w / 256, 256>>>((const float4*)Wk, (uint2*)wkh, (uint2*)wkl, n4w);
    split_kernel<<<n4w / 256, 256>>>((const float4*)Wv, (uint2*)wvh, (uint2*)wvl, n4w);
    split_kernel<<<n4w / 256, 256>>>((const float4*)Wo, (uint2*)woh, (uint2*)wol, n4w);
    maskbits_kernel<<<(int)((size_t)BB * SS * (SS / 32) / 8), 256>>>(mask, mb);

    dim3 gg(DD / 128, MTOK / 128);  // (8, 64)
    gemm_mma<<<gg, 256, GEMM_SMEM>>>(xqh, xql, wqh, wql, nullptr, qh, ql, MTOK, DD, DD, 1);
    gemm_mma<<<gg, 256, GEMM_SMEM>>>(xkh, xkl, wkh, wkl, nullptr, kh, kl, MTOK, DD, DD, 1);
    gemm_mma<<<gg, 256, GEMM_SMEM>>>(xvh, xvl, wvh, wvl, nullptr, vh, vl, MTOK, DD, DD, 1);

    attn_tc<<<dim3(SS / 64, HH, BB), 128, ATTN_SMEM>>>(qh, ql, kh, kl, vh, vl, mb, oh, ol);

    gemm_mma<<<gg, 256, GEMM_SMEM>>>(oh, ol, woh, wol, out, nullptr, nullptr, MTOK, DD, DD, 0);
}

// round 6
// speedup vs baseline: 1.0988x; 1.0634x over previous
#include <cuda_runtime.h>
#include <cuda_bf16.h>
#include <cstdint>
#include <cstddef>

#define BB 4
#define SS 2048
#define DD 1024
#define HH 16
#define MTOK (BB*SS)

// ---------------- scratch (__device__ globals; allocs forbidden) ----------
__device__ __nv_bfloat16 g_xqh[MTOK*DD], g_xql[MTOK*DD];
__device__ __nv_bfloat16 g_xkh[MTOK*DD], g_xkl[MTOK*DD];
__device__ __nv_bfloat16 g_xvh[MTOK*DD], g_xvl[MTOK*DD];
__device__ __nv_bfloat16 g_wqh[DD*DD], g_wql[DD*DD];
__device__ __nv_bfloat16 g_wkh[DD*DD], g_wkl[DD*DD];
__device__ __nv_bfloat16 g_wvh[DD*DD], g_wvl[DD*DD];
__device__ __nv_bfloat16 g_woh[DD*DD], g_wol[DD*DD];
__device__ __nv_bfloat16 g_qh[MTOK*DD], g_ql[MTOK*DD];
__device__ __nv_bfloat16 g_kh[MTOK*DD], g_kl[MTOK*DD];
__device__ __nv_bfloat16 g_vh[MTOK*DD], g_vl[MTOK*DD];
__device__ __nv_bfloat16 g_oh[MTOK*DD], g_ol[MTOK*DD];
__device__ uint32_t g_mbits[(size_t)BB*SS*(SS/32)];

// ---------------- helpers --------------------------------------------------
__device__ __forceinline__ uint32_t smem_u32(const void* p) {
    return (uint32_t)__cvta_generic_to_shared(p);
}
__device__ __forceinline__ void mma16816(float* c, const uint32_t* a, const uint32_t* b) {
    asm volatile(
        "mma.sync.aligned.m16n8k16.row.col.f32.bf16.bf16.f32 "
        "{%0,%1,%2,%3},{%4,%5,%6,%7},{%8,%9},{%0,%1,%2,%3};"
        : "+f"(c[0]), "+f"(c[1]), "+f"(c[2]), "+f"(c[3])
        : "r"(a[0]), "r"(a[1]), "r"(a[2]), "r"(a[3]), "r"(b[0]), "r"(b[1]));
}
__device__ __forceinline__ void ldsm_x4(uint32_t* r, const void* p) {
    uint32_t a = smem_u32(p);
    asm volatile("ldmatrix.sync.aligned.m8n8.x4.shared.b16 {%0,%1,%2,%3},[%4];"
                 : "=r"(r[0]), "=r"(r[1]), "=r"(r[2]), "=r"(r[3]) : "r"(a));
}
__device__ __forceinline__ void ldsm_x4t(uint32_t* r, const void* p) {
    uint32_t a = smem_u32(p);
    asm volatile("ldmatrix.sync.aligned.m8n8.x4.trans.shared.b16 {%0,%1,%2,%3},[%4];"
                 : "=r"(r[0]), "=r"(r[1]), "=r"(r[2]), "=r"(r[3]) : "r"(a));
}
__device__ __forceinline__ void split2(float f0, float f1, uint32_t& hi, uint32_t& lo) {
    __nv_bfloat162 h = __floats2bfloat162_rn(f0, f1);
    float r0 = f0 - __bfloat162float(h.x);
    float r1 = f1 - __bfloat162float(h.y);
    hi = *reinterpret_cast<uint32_t*>(&h);
    __nv_bfloat162 l = __floats2bfloat162_rn(r0, r1);
    lo = *reinterpret_cast<uint32_t*>(&l);
}
__device__ __forceinline__ void cp16(void* s, const void* g) {
    uint32_t sa = smem_u32(s);
    asm volatile("cp.async.cg.shared.global [%0], [%1], 16;" :: "r"(sa), "l"(g));
}
#define CP_COMMIT() asm volatile("cp.async.commit_group;" ::: "memory")
#define CP_WAIT(n)  asm volatile("cp.async.wait_group %0;" :: "n"(n) : "memory")

// ---------------- prepass kernels ------------------------------------------
__global__ void split_kernel(const float4* __restrict__ x, uint2* __restrict__ h,
                             uint2* __restrict__ l, int n4) {
    int i = blockIdx.x * 256 + threadIdx.x;
    if (i < n4) {
        float4 v = x[i];
        uint2 hh, ll;
        split2(v.x, v.y, hh.x, ll.x);
        split2(v.z, v.w, hh.y, ll.y);
        h[i] = hh; l[i] = ll;
    }
}
__global__ void maskbits_kernel(const int* __restrict__ m, uint32_t* __restrict__ bits) {
    size_t w = (size_t)blockIdx.x * 8 + (threadIdx.x >> 5);
    int lane = threadIdx.x & 31;
    int v = m[w * 32 + lane];
    uint32_t b = __ballot_sync(0xffffffffu, v != 0);
    if (lane == 0) bits[w] = b;
}

// ---------------- GEMM: C[M,N] = A[M,K] W[N,K]^T (bf16x3, 3-stage pipe) ----
// Block tile 128x256, 8 warps (2x4), warp tile 64x64, k-tile 32.
#define GST 40
#define G_AH 0
#define G_AL (128*GST)
#define G_WH (2*128*GST)
#define G_WL (2*128*GST + 256*GST)
#define GSTAGE (2*128*GST + 2*256*GST)   // 30720 elems

__global__ __launch_bounds__(256) void gemm_mma(
    const __nv_bfloat16* __restrict__ Ah, const __nv_bfloat16* __restrict__ Al,
    const __nv_bfloat16* __restrict__ Wh, const __nv_bfloat16* __restrict__ Wl,
    float* __restrict__ Cf, __nv_bfloat16* __restrict__ Ch, __nv_bfloat16* __restrict__ Cl,
    int M, int N, int K, int split_out)
{
    extern __shared__ __align__(16) __nv_bfloat16 sg[];   // 3 stages

    const int tid = threadIdx.x, lane = tid & 31, w = tid >> 5;
    const int g = lane >> 2, t4 = lane & 3, l15 = lane & 15;
    const int m0 = (w >> 2) * 64, n0 = (w & 3) * 64;
    const int bm = blockIdx.y * 128, bn = blockIdx.x * 256;

    const __nv_bfloat16* pAh = Ah + (size_t)bm * K;
    const __nv_bfloat16* pAl = Al + (size_t)bm * K;
    const __nv_bfloat16* pWh = Wh + (size_t)bn * K;
    const __nv_bfloat16* pWl = Wl + (size_t)bn * K;

    auto stage = [&](int buf, int k0) {
        __nv_bfloat16* st = sg + buf * GSTAGE;
#pragma unroll
        for (int it = 0; it < 12; ++it) {
            int c = it * 256 + tid;
            if (c < 512) {
                int r = c >> 2, u = c & 3;
                cp16(st + G_AH + r * GST + u * 8, pAh + (size_t)r * K + k0 + u * 8);
            } else if (c < 1024) {
                int cc = c - 512, r = cc >> 2, u = cc & 3;
                cp16(st + G_AL + r * GST + u * 8, pAl + (size_t)r * K + k0 + u * 8);
            } else if (c < 2048) {
                int cc = c - 1024, r = cc >> 2, u = cc & 3;
                cp16(st + G_WH + r * GST + u * 8, pWh + (size_t)r * K + k0 + u * 8);
            } else {
                int cc = c - 2048, r = cc >> 2, u = cc & 3;
                cp16(st + G_WL + r * GST + u * 8, pWl + (size_t)r * K + k0 + u * 8);
            }
        }
    };

    float acc[4][8][4];
#pragma unroll
    for (int i = 0; i < 4; ++i)
#pragma unroll
        for (int j = 0; j < 8; ++j)
#pragma unroll
            for (int c = 0; c < 4; ++c) acc[i][j][c] = 0.f;

    const int NST = K / 32;           // 32
    stage(0, 0);  CP_COMMIT();
    stage(1, 32); CP_COMMIT();

    for (int kt = 0; kt < NST; ++kt) {
        if (kt + 1 < NST) CP_WAIT(1); else CP_WAIT(0);
        __syncthreads();
        if (kt + 2 < NST) { stage((kt + 2) % 3, (kt + 2) * 32); CP_COMMIT(); }

        const __nv_bfloat16* st = sg + (kt % 3) * GSTAGE;
#pragma unroll
        for (int ks = 0; ks < 32; ks += 16) {
            uint32_t ah[4][4], al[4][4];
#pragma unroll
            for (int mt = 0; mt < 4; ++mt) {
                const int ro = (m0 + mt * 16 + l15) * GST + ks + (lane >> 4) * 8;
                ldsm_x4(ah[mt], st + G_AH + ro);
                ldsm_x4(al[mt], st + G_AL + ro);
            }
#pragma unroll
            for (int nt2 = 0; nt2 < 4; ++nt2) {
                const int ro = (n0 + nt2 * 16 + l15) * GST + ks + (lane >> 4) * 8;
                uint32_t wh4[4], wl4[4];
                ldsm_x4(wh4, st + G_WH + ro);
                ldsm_x4(wl4, st + G_WL + ro);
                uint32_t bhe[2] = {wh4[0], wh4[2]}, bho[2] = {wh4[1], wh4[3]};
                uint32_t ble[2] = {wl4[0], wl4[2]}, blo[2] = {wl4[1], wl4[3]};
#pragma unroll
                for (int mt = 0; mt < 4; ++mt) {
                    mma16816(acc[mt][2*nt2],   ah[mt], bhe);
                    mma16816(acc[mt][2*nt2],   ah[mt], ble);
                    mma16816(acc[mt][2*nt2],   al[mt], bhe);
                    mma16816(acc[mt][2*nt2+1], ah[mt], bho);
                    mma16816(acc[mt][2*nt2+1], ah[mt], blo);
                    mma16816(acc[mt][2*nt2+1], al[mt], bho);
                }
            }
        }
    }

#pragma unroll
    for (int mt = 0; mt < 4; ++mt)
#pragma unroll
        for (int nt = 0; nt < 8; ++nt) {
            int row = bm + m0 + mt * 16 + g;
            int col = bn + n0 + nt * 8 + 2 * t4;
            if (split_out) {
                uint32_t hh, ll;
                split2(acc[mt][nt][0], acc[mt][nt][1], hh, ll);
                *(uint32_t*)&Ch[(size_t)row * N + col] = hh;
                *(uint32_t*)&Cl[(size_t)row * N + col] = ll;
                split2(acc[mt][nt][2], acc[mt][nt][3], hh, ll);
                *(uint32_t*)&Ch[(size_t)(row + 8) * N + col] = hh;
                *(uint32_t*)&Cl[(size_t)(row + 8) * N + col] = ll;
            } else {
                *(float2*)(Cf + (size_t)row * N + col) =
                    make_float2(acc[mt][nt][0], acc[mt][nt][1]);
                *(float2*)(Cf + (size_t)(row + 8) * N + col) =
                    make_float2(acc[mt][nt][2], acc[mt][nt][3]);
            }
        }
}

// ---------------- fused attention: 128-query tile, 8 warps -----------------
#define TS 72
#define A_QH 0
#define A_QL (128*TS)
#define A_KV (2*128*TS)
#define A_KVSZ (4*64*TS)      // Kh,Kl,Vh,Vl per buffer

__global__ __launch_bounds__(256) void attn_tc(
    const __nv_bfloat16* __restrict__ Qh, const __nv_bfloat16* __restrict__ Ql,
    const __nv_bfloat16* __restrict__ Kh, const __nv_bfloat16* __restrict__ Kl,
    const __nv_bfloat16* __restrict__ Vh, const __nv_bfloat16* __restrict__ Vl,
    const uint32_t* __restrict__ mbits,
    __nv_bfloat16* __restrict__ Oh, __nv_bfloat16* __restrict__ Ol)
{
    extern __shared__ __align__(16) __nv_bfloat16 sm[];

    const int b = blockIdx.z, h = blockIdx.y, s0 = blockIdx.x * 128;
    const int tid = threadIdx.x, lane = tid & 31, w = tid >> 5;
    const int g = lane >> 2, t4 = lane & 3;
    const int m0 = w * 16, l15 = lane & 15;

    // stage Q (128 rows x 64, hi+lo)
    const __nv_bfloat16* qhp = Qh + (size_t)(b * SS + s0) * DD + h * 64;
    const __nv_bfloat16* qlp = Ql + (size_t)(b * SS + s0) * DD + h * 64;
#pragma unroll
    for (int it = 0; it < 8; ++it) {
        int c = it * 256 + tid;
        int r = (c & 1023) >> 3, u = c & 7;
        if (c < 1024) cp16(&sm[A_QH + r * TS + u * 8], qhp + (size_t)r * DD + u * 8);
        else          cp16(&sm[A_QL + r * TS + u * 8], qlp + (size_t)r * DD + u * 8);
    }

    const __nv_bfloat16* khp = Kh + (size_t)(b * SS) * DD + h * 64;
    const __nv_bfloat16* klp = Kl + (size_t)(b * SS) * DD + h * 64;
    const __nv_bfloat16* vhp = Vh + (size_t)(b * SS) * DD + h * 64;
    const __nv_bfloat16* vlp = Vl + (size_t)(b * SS) * DD + h * 64;

    auto stageKV = [&](int buf, int t0) {
        __nv_bfloat16* st = sm + A_KV + buf * A_KVSZ;
#pragma unroll
        for (int it = 0; it < 8; ++it) {
            int c = it * 256 + tid;
            int mat = c >> 9, r = (c >> 3) & 63, u = c & 7;
            const __nv_bfloat16* src =
                (mat == 0 ? khp : mat == 1 ? klp : mat == 2 ? vhp : vlp)
                + (size_t)(t0 + r) * DD + u * 8;
            cp16(st + mat * (64 * TS) + r * TS + u * 8, src);
        }
    };

    stageKV(0, 0);
    CP_COMMIT();   // group0 = Q + KV0

    float m_i[2] = {-1e30f, -1e30f}, l_i[2] = {0.f, 0.f};
    float oacc[8][4];
#pragma unroll
    for (int nt = 0; nt < 8; ++nt)
#pragma unroll
        for (int c = 0; c < 4; ++c) oacc[nt][c] = 0.f;

    const uint32_t* mb0 = mbits + ((size_t)b * SS + s0 + m0 + g) * (SS / 32);
    const uint32_t* mb8 = mb0 + 8 * (SS / 32);

    for (int i = 0; i < SS / 64; ++i) {
        const int t0 = i * 64, buf = i & 1;
        __syncthreads();
        if (i + 1 < SS / 64) { stageKV(buf ^ 1, t0 + 64); CP_COMMIT(); CP_WAIT(1); }
        else CP_WAIT(0);
        __syncthreads();

        const __nv_bfloat16* bKh = sm + A_KV + buf * A_KVSZ;
        const __nv_bfloat16* bKl = bKh + 64 * TS;
        const __nv_bfloat16* bVh = bKl + 64 * TS;
        const __nv_bfloat16* bVl = bVh + 64 * TS;

        // ---- S = Q K^T ----
        float sc[8][4];
#pragma unroll
        for (int nt = 0; nt < 8; ++nt)
#pragma unroll
            for (int c = 0; c < 4; ++c) sc[nt][c] = 0.f;

#pragma unroll
        for (int ks = 0; ks < 64; ks += 16) {
            uint32_t qfh[4], qfl[4];
            const int qo = (m0 + l15) * TS + ks + (lane >> 4) * 8;
            ldsm_x4(qfh, &sm[A_QH + qo]);
            ldsm_x4(qfl, &sm[A_QL + qo]);
#pragma unroll
            for (int nt2 = 0; nt2 < 4; ++nt2) {
                const int ro = (nt2 * 16 + l15) * TS + ks + (lane >> 4) * 8;
                uint32_t kh4[4], kl4[4];
                ldsm_x4(kh4, bKh + ro);
                ldsm_x4(kl4, bKl + ro);
                uint32_t bhe[2] = {kh4[0], kh4[2]}, bho[2] = {kh4[1], kh4[3]};
                uint32_t ble[2] = {kl4[0], kl4[2]}, blo[2] = {kl4[1], kl4[3]};
                mma16816(sc[2*nt2],   qfh, bhe);
                mma16816(sc[2*nt2],   qfh, ble);
                mma16816(sc[2*nt2],   qfl, bhe);
                mma16816(sc[2*nt2+1], qfh, bho);
                mma16816(sc[2*nt2+1], qfh, blo);
                mma16816(sc[2*nt2+1], qfl, bho);
            }
        }

        // ---- mask + scale ----
        uint32_t wa0 = mb0[t0 >> 5], wb0 = mb0[(t0 >> 5) + 1];
        uint32_t wa8 = mb8[t0 >> 5], wb8 = mb8[(t0 >> 5) + 1];
        if ((wa0 & wb0 & wa8 & wb8) == 0xffffffffu) {
#pragma unroll
            for (int nt = 0; nt < 8; ++nt)
#pragma unroll
                for (int c = 0; c < 4; ++c) sc[nt][c] *= 0.125f;
        } else {
#pragma unroll
            for (int nt = 0; nt < 8; ++nt) {
                int c = nt * 8 + 2 * t4;
                uint32_t s0w = (c & 32) ? wb0 : wa0;
                uint32_t s8w = (c & 32) ? wb8 : wa8;
                int sh = c & 31;
                sc[nt][0] = ((s0w >> sh) & 1)       ? sc[nt][0] * 0.125f : -1e10f;
                sc[nt][1] = ((s0w >> (sh + 1)) & 1) ? sc[nt][1] * 0.125f : -1e10f;
                sc[nt][2] = ((s8w >> sh) & 1)       ? sc[nt][2] * 0.125f : -1e10f;
                sc[nt][3] = ((s8w >> (sh + 1)) & 1) ? sc[nt][3] * 0.125f : -1e10f;
            }
        }

        // ---- online softmax ----
        float mx0 = -1e30f, mx1 = -1e30f;
#pragma unroll
        for (int nt = 0; nt < 8; ++nt) {
            mx0 = fmaxf(mx0, fmaxf(sc[nt][0], sc[nt][1]));
            mx1 = fmaxf(mx1, fmaxf(sc[nt][2], sc[nt][3]));
        }
        mx0 = fmaxf(mx0, __shfl_xor_sync(0xffffffffu, mx0, 1));
        mx0 = fmaxf(mx0, __shfl_xor_sync(0xffffffffu, mx0, 2));
        mx1 = fmaxf(mx1, __shfl_xor_sync(0xffffffffu, mx1, 1));
        mx1 = fmaxf(mx1, __shfl_xor_sync(0xffffffffu, mx1, 2));

        float mn0 = fmaxf(m_i[0], mx0), mn1 = fmaxf(m_i[1], mx1);
        float corr0 = __expf(m_i[0] - mn0), corr1 = __expf(m_i[1] - mn1);
        m_i[0] = mn0; m_i[1] = mn1;

        float sum0 = 0.f, sum1 = 0.f;
#pragma unroll
        for (int nt = 0; nt < 8; ++nt) {
            sc[nt][0] = __expf(sc[nt][0] - mn0);
            sc[nt][1] = __expf(sc[nt][1] - mn0);
            sc[nt][2] = __expf(sc[nt][2] - mn1);
            sc[nt][3] = __expf(sc[nt][3] - mn1);
            sum0 += sc[nt][0] + sc[nt][1];
            sum1 += sc[nt][2] + sc[nt][3];
        }
        sum0 += __shfl_xor_sync(0xffffffffu, sum0, 1);
        sum0 += __shfl_xor_sync(0xffffffffu, sum0, 2);
        sum1 += __shfl_xor_sync(0xffffffffu, sum1, 1);
        sum1 += __shfl_xor_sync(0xffffffffu, sum1, 2);
        l_i[0] = l_i[0] * corr0 + sum0;
        l_i[1] = l_i[1] * corr1 + sum1;
#pragma unroll
        for (int nt = 0; nt < 8; ++nt) {
            oacc[nt][0] *= corr0; oacc[nt][1] *= corr0;
            oacc[nt][2] *= corr1; oacc[nt][3] *= corr1;
        }

        // ---- O += P V  (P in registers; V via ldmatrix.x4.trans) ----
#pragma unroll
        for (int j = 0; j < 4; ++j) {
            uint32_t ph[4], pl[4];
            split2(sc[2*j][0],   sc[2*j][1],   ph[0], pl[0]);
            split2(sc[2*j][2],   sc[2*j][3],   ph[1], pl[1]);
            split2(sc[2*j+1][0], sc[2*j+1][1], ph[2], pl[2]);
            split2(sc[2*j+1][2], sc[2*j+1][3], ph[3], pl[3]);
#pragma unroll
            for (int nt2 = 0; nt2 < 4; ++nt2) {
                const int ro = (j * 16 + l15) * TS + nt2 * 16 + (lane >> 4) * 8;
                uint32_t vh4[4], vl4[4];
                ldsm_x4t(vh4, bVh + ro);
                ldsm_x4t(vl4, bVl + ro);
                uint32_t vhe[2] = {vh4[0], vh4[1]}, vho[2] = {vh4[2], vh4[3]};
                uint32_t vle[2] = {vl4[0], vl4[1]}, vlo[2] = {vl4[2], vl4[3]};
                mma16816(oacc[2*nt2],   ph, vhe);
                mma16816(oacc[2*nt2],   ph, vle);
                mma16816(oacc[2*nt2],   pl, vhe);
                mma16816(oacc[2*nt2+1], ph, vho);
                mma16816(oacc[2*nt2+1], ph, vlo);
                mma16816(oacc[2*nt2+1], pl, vho);
            }
        }
    }

    // ---- epilogue: normalize, split, store bf16 hi/lo ----
    float inv0 = __fdividef(1.f, l_i[0]);
    float inv1 = __fdividef(1.f, l_i[1]);
    size_t r0 = (size_t)(b * SS + s0 + m0 + g) * DD + h * 64;
    size_t r8 = r0 + (size_t)8 * DD;
#pragma unroll
    for (int nt = 0; nt < 8; ++nt) {
        int col = nt * 8 + 2 * t4;
        uint32_t hh, ll;
        split2(oacc[nt][0] * inv0, oacc[nt][1] * inv0, hh, ll);
        *(uint32_t*)&Oh[r0 + col] = hh; *(uint32_t*)&Ol[r0 + col] = ll;
        split2(oacc[nt][2] * inv1, oacc[nt][3] * inv1, hh, ll);
        *(uint32_t*)&Oh[r8 + col] = hh; *(uint32_t*)&Ol[r8 + col] = ll;
    }
}

// ---------------------------------------------------------------------------
extern "C" void kernel_launch(void* const* d_in, const int* in_sizes, int n_in,
                              void* d_out, int out_size)
{
    const float* queries = (const float*)d_in[0];
    const float* keys    = (const float*)d_in[1];
    const float* values  = (const float*)d_in[2];
    const int*   mask    = (const int*)  d_in[3];
    const float* Wq = (const float*)d_in[4];
    const float* Wk = (const float*)d_in[5];
    const float* Wv = (const float*)d_in[6];
    const float* Wo = (const float*)d_in[7];
    float* out = (float*)d_out;

    __nv_bfloat16 *xqh,*xql,*xkh,*xkl,*xvh,*xvl, *wqh,*wql,*wkh,*wkl,*wvh,*wvl,*woh,*wol;
    __nv_bfloat16 *qh,*ql,*kh,*kl,*vh,*vl,*oh,*ol;
    uint32_t* mb;
    cudaGetSymbolAddress((void**)&xqh, g_xqh); cudaGetSymbolAddress((void**)&xql, g_xql);
    cudaGetSymbolAddress((void**)&xkh, g_xkh); cudaGetSymbolAddress((void**)&xkl, g_xkl);
    cudaGetSymbolAddress((void**)&xvh, g_xvh); cudaGetSymbolAddress((void**)&xvl, g_xvl);
    cudaGetSymbolAddress((void**)&wqh, g_wqh); cudaGetSymbolAddress((void**)&wql, g_wql);
    cudaGetSymbolAddress((void**)&wkh, g_wkh); cudaGetSymbolAddress((void**)&wkl, g_wkl);
    cudaGetSymbolAddress((void**)&wvh, g_wvh); cudaGetSymbolAddress((void**)&wvl, g_wvl);
    cudaGetSymbolAddress((void**)&woh, g_woh); cudaGetSymbolAddress((void**)&wol, g_wol);
    cudaGetSymbolAddress((void**)&qh, g_qh); cudaGetSymbolAddress((void**)&ql, g_ql);
    cudaGetSymbolAddress((void**)&kh, g_kh); cudaGetSymbolAddress((void**)&kl, g_kl);
    cudaGetSymbolAddress((void**)&vh, g_vh); cudaGetSymbolAddress((void**)&vl, g_vl);
    cudaGetSymbolAddress((void**)&oh, g_oh); cudaGetSymbolAddress((void**)&ol, g_ol);
    cudaGetSymbolAddress((void**)&mb, g_mbits);

    const int GEMM_SMEM = 3 * GSTAGE * (int)sizeof(__nv_bfloat16);            // 184320
    cudaFuncSetAttribute(gemm_mma, cudaFuncAttributeMaxDynamicSharedMemorySize, GEMM_SMEM);
    const int ATTN_SMEM = (2 * 128 * TS + 2 * A_KVSZ) * (int)sizeof(__nv_bfloat16); // 110592
    cudaFuncSetAttribute(attn_tc, cudaFuncAttributeMaxDynamicSharedMemorySize, ATTN_SMEM);

    const int n4i = MTOK * DD / 4, n4w = DD * DD / 4;
    split_kernel<<<n4i / 256, 256>>>((const float4*)queries, (uint2*)xqh, (uint2*)xql, n4i);
    split_kernel<<<n4i / 256, 256>>>((const float4*)keys,    (uint2*)xkh, (uint2*)xkl, n4i);
    split_kernel<<<n4i / 256, 256>>>((const float4*)values,  (uint2*)xvh, (uint2*)xvl, n4i);
    split_kernel<<<n4w / 256, 256>>>((const float4*)Wq, (uint2*)wqh, (uint2*)wql, n4w);
    split_kernel<<<n4w / 256, 256>>>((const float4*)Wk, (uint2*)wkh, (uint2*)wkl, n4w);
    split_kernel<<<n4w / 256, 256>>>((const float4*)Wv, (uint2*)wvh, (uint2*)wvl, n4w);
    split_kernel<<<n4w / 256, 256>>>((const float4*)Wo, (uint2*)woh, (uint2*)wol, n4w);
    maskbits_kernel<<<(int)((size_t)BB * SS * (SS / 32) / 8), 256>>>(mask, mb);

    dim3 gg(DD / 256, MTOK / 128);  // (4, 64)
    gemm_mma<<<gg, 256, GEMM_SMEM>>>(xqh, xql, wqh, wql, nullptr, qh, ql, MTOK, DD, DD, 1);
    gemm_mma<<<gg, 256, GEMM_SMEM>>>(xkh, xkl, wkh, wkl, nullptr, kh, kl, MTOK, DD, DD, 1);
    gemm_mma<<<gg, 256, GEMM_SMEM>>>(xvh, xvl, wvh, wvl, nullptr, vh, vl, MTOK, DD, DD, 1);

    attn_tc<<<dim3(SS / 128, HH, BB), 256, ATTN_SMEM>>>(qh, ql, kh, kl, vh, vl, mb, oh, ol);

    gemm_mma<<<gg, 256, GEMM_SMEM>>>(oh, ol, woh, wol, out, nullptr, nullptr, MTOK, DD, DD, 0);
}